// round 1
// baseline (speedup 1.0000x reference)
#include <cuda_runtime.h>

#define N_NODES 10000
#define N_EDGES 640000
#define F_IN    128
#define F_OUT   512

// ---------------- device scratch (no allocations allowed) ----------------
__device__ int   g_deg[N_NODES];
__device__ int   g_off[N_NODES + 1];
__device__ int   g_cur[N_NODES];
__device__ int   g_csr[N_EDGES];
__device__ float g_h[N_NODES * F_IN];

// ---------------- 1. zero degree ----------------
__global__ void k_zero() {
    int i = blockIdx.x * blockDim.x + threadIdx.x;
    if (i < N_NODES) g_deg[i] = 0;
}

// ---------------- 2. count in-degree ----------------
__global__ void k_deg(const int* __restrict__ dst) {
    int e = blockIdx.x * blockDim.x + threadIdx.x;
    if (e < N_EDGES) atomicAdd(&g_deg[dst[e]], 1);
}

// ---------------- 3. exclusive scan (single block, 1024 threads) ----------------
__global__ void k_scan() {
    __shared__ int part[1024];
    const int CH = 10;  // 1024 * 10 = 10240 >= N_NODES
    int t = threadIdx.x;
    int base = t * CH;
    int loc[CH];
    int s = 0;
#pragma unroll
    for (int i = 0; i < CH; i++) {
        int idx = base + i;
        int v = (idx < N_NODES) ? g_deg[idx] : 0;
        loc[i] = s;
        s += v;
    }
    part[t] = s;
    __syncthreads();
    // Hillis-Steele inclusive scan over 1024 partials
    for (int off = 1; off < 1024; off <<= 1) {
        int v = part[t];
        int a = (t >= off) ? part[t - off] : 0;
        __syncthreads();
        part[t] = v + a;
        __syncthreads();
    }
    int excl = (t == 0) ? 0 : part[t - 1];
#pragma unroll
    for (int i = 0; i < CH; i++) {
        int idx = base + i;
        if (idx < N_NODES) {
            int o = excl + loc[i];
            g_off[idx] = o;
            g_cur[idx] = o;
        }
    }
    if (t == 1023) g_off[N_NODES] = part[1023];
}

// ---------------- 4. fill CSR (src ids bucketed by dst) ----------------
__global__ void k_fill(const int* __restrict__ src, const int* __restrict__ dst) {
    int e = blockIdx.x * blockDim.x + threadIdx.x;
    if (e < N_EDGES) {
        int d = dst[e];
        int p = atomicAdd(&g_cur[d], 1);
        g_csr[p] = src[e];
    }
}

// ---------------- 5. gather-mean: one warp per destination node ----------------
__global__ void k_gather(const float* __restrict__ x) {
    int gw = (blockIdx.x * blockDim.x + threadIdx.x) >> 5;
    int lane = threadIdx.x & 31;
    if (gw >= N_NODES) return;

    const float4* __restrict__ x4 = (const float4*)x;  // row = 32 float4s
    int beg = g_off[gw];
    int end = g_off[gw + 1];

    float ax = 0.f, ay = 0.f, az = 0.f, aw = 0.f;
    int j = beg;
    for (; j + 3 < end; j += 4) {
        int s0 = g_csr[j + 0];
        int s1 = g_csr[j + 1];
        int s2 = g_csr[j + 2];
        int s3 = g_csr[j + 3];
        float4 v0 = x4[s0 * 32 + lane];
        float4 v1 = x4[s1 * 32 + lane];
        float4 v2 = x4[s2 * 32 + lane];
        float4 v3 = x4[s3 * 32 + lane];
        ax += (v0.x + v1.x) + (v2.x + v3.x);
        ay += (v0.y + v1.y) + (v2.y + v3.y);
        az += (v0.z + v1.z) + (v2.z + v3.z);
        aw += (v0.w + v1.w) + (v2.w + v3.w);
    }
    for (; j < end; ++j) {
        int s = g_csr[j];
        float4 v = x4[s * 32 + lane];
        ax += v.x; ay += v.y; az += v.z; aw += v.w;
    }

    int d = end - beg;
    float4 o;
    if (d > 0) {
        float inv = 1.0f / (float)d;
        o.x = ax * inv; o.y = ay * inv; o.z = az * inv; o.w = aw * inv;
    } else {
        o = x4[gw * 32 + lane];  // zero-in-degree nodes keep inputs
    }
    ((float4*)g_h)[gw * 32 + lane] = o;
}

// ---------------- 6. GEMM: out[N,512] = h[N,128] @ W[128,512] + b ----------------
// BM=64, BN=64, full K=128 A-tile resident in SMEM, B streamed in 4 chunks of 32.
// 256 threads (16x16), 4x4 micro-tile per thread.
#define SP 68  // padded pitch (floats) for the [k][m]/[k][n] smem tiles

__global__ void k_gemm(const float* __restrict__ W, const float* __restrict__ b,
                       float* __restrict__ out) {
    __shared__ float As[128 * SP];  // 34816 B  (A transposed: As[k][m])
    __shared__ float Bs[32 * SP];   //  8704 B  (Bs[kk][n])

    int tid = threadIdx.x;
    int tx = tid & 15;       // n micro-tile index
    int ty = tid >> 4;       // m micro-tile index
    int m0 = blockIdx.x * 64;
    int n0 = blockIdx.y * 64;

    // Load A tile: 64 rows x 128 k, coalesced float4 reads, transposed store.
    const float4* __restrict__ h4 = (const float4*)g_h;
    for (int i = tid; i < 64 * 32; i += 256) {
        int m = i >> 5;
        int kq = i & 31;
        float4 v = (m0 + m < N_NODES) ? h4[(m0 + m) * 32 + kq]
                                      : make_float4(0.f, 0.f, 0.f, 0.f);
        As[(4 * kq + 0) * SP + m] = v.x;
        As[(4 * kq + 1) * SP + m] = v.y;
        As[(4 * kq + 2) * SP + m] = v.z;
        As[(4 * kq + 3) * SP + m] = v.w;
    }

    const float4* __restrict__ W4 = (const float4*)W;
    float acc[4][4] = {};

    for (int kc = 0; kc < 4; kc++) {
        __syncthreads();  // (also orders As writes before first use)
        // Load B chunk: 32 k-rows x 64 n-cols
        for (int i = tid; i < 32 * 16; i += 256) {
            int kk = i >> 4;
            int nq = i & 15;
            float4 v = W4[(kc * 32 + kk) * (F_OUT / 4) + (n0 >> 2) + nq];
            *(float4*)&Bs[kk * SP + nq * 4] = v;
        }
        __syncthreads();

#pragma unroll
        for (int kk = 0; kk < 32; kk++) {
            int k = kc * 32 + kk;
            float4 a  = *(const float4*)&As[k * SP + ty * 4];
            float4 bb = *(const float4*)&Bs[kk * SP + tx * 4];
            acc[0][0] += a.x * bb.x; acc[0][1] += a.x * bb.y;
            acc[0][2] += a.x * bb.z; acc[0][3] += a.x * bb.w;
            acc[1][0] += a.y * bb.x; acc[1][1] += a.y * bb.y;
            acc[1][2] += a.y * bb.z; acc[1][3] += a.y * bb.w;
            acc[2][0] += a.z * bb.x; acc[2][1] += a.z * bb.y;
            acc[2][2] += a.z * bb.z; acc[2][3] += a.z * bb.w;
            acc[3][0] += a.w * bb.x; acc[3][1] += a.w * bb.y;
            acc[3][2] += a.w * bb.z; acc[3][3] += a.w * bb.w;
        }
    }

    float4 bvec = *(const float4*)&b[n0 + tx * 4];
#pragma unroll
    for (int r = 0; r < 4; r++) {
        int m = m0 + ty * 4 + r;
        if (m < N_NODES) {
            float4 o;
            o.x = acc[r][0] + bvec.x;
            o.y = acc[r][1] + bvec.y;
            o.z = acc[r][2] + bvec.z;
            o.w = acc[r][3] + bvec.w;
            *(float4*)&out[m * F_OUT + n0 + tx * 4] = o;
        }
    }
}

// ---------------- launch ----------------
extern "C" void kernel_launch(void* const* d_in, const int* in_sizes, int n_in,
                              void* d_out, int out_size) {
    const float* x   = (const float*)d_in[0];
    const int*   src = (const int*)d_in[1];
    const int*   dst = (const int*)d_in[2];
    const float* W   = (const float*)d_in[3];
    const float* b   = (const float*)d_in[4];
    float* out = (float*)d_out;

    k_zero<<<(N_NODES + 255) / 256, 256>>>();
    k_deg<<<(N_EDGES + 255) / 256, 256>>>(dst);
    k_scan<<<1, 1024>>>();
    k_fill<<<(N_EDGES + 255) / 256, 256>>>(src, dst);
    k_gather<<<(N_NODES * 32 + 255) / 256, 256>>>(x);
    dim3 gg((N_NODES + 63) / 64, F_OUT / 64);
    k_gemm<<<gg, 256>>>(W, b, out);
}

// round 2
// speedup vs baseline: 1.0512x; 1.0512x over previous
#include <cuda_runtime.h>

#define N_NODES 10000
#define N_EDGES 640000
#define F_IN    128
#define F_OUT   512

// ---------------- device scratch (no allocations allowed) ----------------
__device__ int   g_deg[N_NODES];
__device__ int   g_off[N_NODES + 1];
__device__ int   g_rank[N_EDGES];
__device__ int   g_csr[N_EDGES];
__device__ float g_h[N_NODES * F_IN];

// ---------------- 1. zero degree ----------------
__global__ void k_zero() {
    int i = blockIdx.x * blockDim.x + threadIdx.x;
    if (i < N_NODES) g_deg[i] = 0;
}

// ---------------- 2. count in-degree + record per-edge rank ----------------
// 4 edges per thread via int4. N_EDGES % 4 == 0.
__global__ void k_deg(const int* __restrict__ dst) {
    int t = blockIdx.x * blockDim.x + threadIdx.x;
    int e = t * 4;
    if (e < N_EDGES) {
        int4 d4 = *(const int4*)&dst[e];
        int r0 = atomicAdd(&g_deg[d4.x], 1);
        int r1 = atomicAdd(&g_deg[d4.y], 1);
        int r2 = atomicAdd(&g_deg[d4.z], 1);
        int r3 = atomicAdd(&g_deg[d4.w], 1);
        *(int4*)&g_rank[e] = make_int4(r0, r1, r2, r3);
    }
}

// ---------------- 3. exclusive scan (single block, 1024 threads) ----------------
__global__ void k_scan() {
    __shared__ int part[1024];
    const int CH = 10;  // 1024 * 10 = 10240 >= N_NODES
    int t = threadIdx.x;
    int base = t * CH;
    int loc[CH];
    int s = 0;
#pragma unroll
    for (int i = 0; i < CH; i++) {
        int idx = base + i;
        int v = (idx < N_NODES) ? g_deg[idx] : 0;
        loc[i] = s;
        s += v;
    }
    part[t] = s;
    __syncthreads();
    for (int off = 1; off < 1024; off <<= 1) {
        int v = part[t];
        int a = (t >= off) ? part[t - off] : 0;
        __syncthreads();
        part[t] = v + a;
        __syncthreads();
    }
    int excl = (t == 0) ? 0 : part[t - 1];
#pragma unroll
    for (int i = 0; i < CH; i++) {
        int idx = base + i;
        if (idx < N_NODES) g_off[idx] = excl + loc[i];
    }
    if (t == 1023) g_off[N_NODES] = part[1023];
}

// ---------------- 4. fill CSR (atomic-free: off[d] + rank[e]) ----------------
__global__ void k_fill(const int* __restrict__ src, const int* __restrict__ dst) {
    int t = blockIdx.x * blockDim.x + threadIdx.x;
    int e = t * 4;
    if (e < N_EDGES) {
        int4 d4 = *(const int4*)&dst[e];
        int4 s4 = *(const int4*)&src[e];
        int4 r4 = *(const int4*)&g_rank[e];
        g_csr[g_off[d4.x] + r4.x] = s4.x;
        g_csr[g_off[d4.y] + r4.y] = s4.y;
        g_csr[g_off[d4.z] + r4.z] = s4.z;
        g_csr[g_off[d4.w] + r4.w] = s4.w;
    }
}

// ---------------- 5. gather-mean: one warp per destination node ----------------
__global__ void k_gather(const float* __restrict__ x) {
    int gw = (blockIdx.x * blockDim.x + threadIdx.x) >> 5;
    int lane = threadIdx.x & 31;
    if (gw >= N_NODES) return;

    const float4* __restrict__ x4 = (const float4*)x;  // row = 32 float4s
    int beg = g_off[gw];
    int end = g_off[gw + 1];

    float ax = 0.f, ay = 0.f, az = 0.f, aw = 0.f;
    int j = beg;
    // unroll 8 for deep L2 MLP
    for (; j + 7 < end; j += 8) {
        int s0 = g_csr[j + 0], s1 = g_csr[j + 1], s2 = g_csr[j + 2], s3 = g_csr[j + 3];
        int s4 = g_csr[j + 4], s5 = g_csr[j + 5], s6 = g_csr[j + 6], s7 = g_csr[j + 7];
        float4 v0 = x4[s0 * 32 + lane];
        float4 v1 = x4[s1 * 32 + lane];
        float4 v2 = x4[s2 * 32 + lane];
        float4 v3 = x4[s3 * 32 + lane];
        float4 v4 = x4[s4 * 32 + lane];
        float4 v5 = x4[s5 * 32 + lane];
        float4 v6 = x4[s6 * 32 + lane];
        float4 v7 = x4[s7 * 32 + lane];
        ax += ((v0.x + v1.x) + (v2.x + v3.x)) + ((v4.x + v5.x) + (v6.x + v7.x));
        ay += ((v0.y + v1.y) + (v2.y + v3.y)) + ((v4.y + v5.y) + (v6.y + v7.y));
        az += ((v0.z + v1.z) + (v2.z + v3.z)) + ((v4.z + v5.z) + (v6.z + v7.z));
        aw += ((v0.w + v1.w) + (v2.w + v3.w)) + ((v4.w + v5.w) + (v6.w + v7.w));
    }
    for (; j < end; ++j) {
        int s = g_csr[j];
        float4 v = x4[s * 32 + lane];
        ax += v.x; ay += v.y; az += v.z; aw += v.w;
    }

    int d = end - beg;
    float4 o;
    if (d > 0) {
        float inv = 1.0f / (float)d;
        o.x = ax * inv; o.y = ay * inv; o.z = az * inv; o.w = aw * inv;
    } else {
        o = x4[gw * 32 + lane];  // zero-in-degree nodes keep inputs
    }
    ((float4*)g_h)[gw * 32 + lane] = o;
}

// ---------------- 6. GEMM: out[N,512] = h[N,128] @ W[128,512] + b ----------------
// BM=128, BN=128, BK=16 double-buffered. 256 threads, 8x8 micro-tile.
#define BM 128
#define BN 128
#define BK 16
#define APITCH (BM + 4)
#define BPITCH (BN + 4)

__global__ void __launch_bounds__(256, 2)
k_gemm(const float* __restrict__ W, const float* __restrict__ b,
       float* __restrict__ out) {
    __shared__ float As[2][BK][APITCH];  // [k][m]
    __shared__ float Bs[2][BK][BPITCH];  // [k][n]

    int tid = threadIdx.x;
    int tx = tid & 15;       // n micro-tile
    int ty = tid >> 4;       // m micro-tile
    int m0 = blockIdx.x * BM;
    int n0 = blockIdx.y * BN;

    const float4* __restrict__ h4 = (const float4*)g_h;
    const float4* __restrict__ W4 = (const float4*)W;

    // loader indices (2 float4 each for A and B per chunk)
    int aid0 = tid * 2, aid1 = tid * 2 + 1;
    int am0 = aid0 >> 2, akq0 = aid0 & 3;
    int am1 = aid1 >> 2, akq1 = aid1 & 3;
    int bid0 = tid * 2, bid1 = tid * 2 + 1;
    int bkk0 = bid0 >> 5, bnq0 = bid0 & 31;
    int bkk1 = bid1 >> 5, bnq1 = bid1 & 31;

    float4 av0, av1, bv0, bv1;

#define LDG_CHUNK(kc)                                                          \
    {                                                                          \
        int r0 = m0 + am0, r1 = m0 + am1;                                      \
        av0 = (r0 < N_NODES) ? h4[r0 * 32 + (kc) * 4 + akq0]                   \
                             : make_float4(0.f, 0.f, 0.f, 0.f);                \
        av1 = (r1 < N_NODES) ? h4[r1 * 32 + (kc) * 4 + akq1]                   \
                             : make_float4(0.f, 0.f, 0.f, 0.f);                \
        bv0 = W4[((kc) * BK + bkk0) * (F_OUT / 4) + (n0 >> 2) + bnq0];         \
        bv1 = W4[((kc) * BK + bkk1) * (F_OUT / 4) + (n0 >> 2) + bnq1];         \
    }

#define STS_CHUNK(buf)                                                         \
    {                                                                          \
        As[buf][4 * akq0 + 0][am0] = av0.x;                                    \
        As[buf][4 * akq0 + 1][am0] = av0.y;                                    \
        As[buf][4 * akq0 + 2][am0] = av0.z;                                    \
        As[buf][4 * akq0 + 3][am0] = av0.w;                                    \
        As[buf][4 * akq1 + 0][am1] = av1.x;                                    \
        As[buf][4 * akq1 + 1][am1] = av1.y;                                    \
        As[buf][4 * akq1 + 2][am1] = av1.z;                                    \
        As[buf][4 * akq1 + 3][am1] = av1.w;                                    \
        *(float4*)&Bs[buf][bkk0][bnq0 * 4] = bv0;                              \
        *(float4*)&Bs[buf][bkk1][bnq1 * 4] = bv1;                              \
    }

    float acc[8][8] = {};

    LDG_CHUNK(0);
    STS_CHUNK(0);
    __syncthreads();

    const int NCHUNK = F_IN / BK;  // 8
#pragma unroll
    for (int kc = 0; kc < NCHUNK; kc++) {
        int cur = kc & 1;
        if (kc + 1 < NCHUNK) LDG_CHUNK(kc + 1);

#pragma unroll
        for (int kk = 0; kk < BK; kk++) {
            float4 a0 = *(const float4*)&As[cur][kk][ty * 8];
            float4 a1 = *(const float4*)&As[cur][kk][ty * 8 + 4];
            float4 b0 = *(const float4*)&Bs[cur][kk][tx * 8];
            float4 b1 = *(const float4*)&Bs[cur][kk][tx * 8 + 4];
            float am[8] = {a0.x, a0.y, a0.z, a0.w, a1.x, a1.y, a1.z, a1.w};
            float bn[8] = {b0.x, b0.y, b0.z, b0.w, b1.x, b1.y, b1.z, b1.w};
#pragma unroll
            for (int r = 0; r < 8; r++)
#pragma unroll
                for (int c = 0; c < 8; c++)
                    acc[r][c] += am[r] * bn[c];
        }

        if (kc + 1 < NCHUNK) {
            __syncthreads();
            STS_CHUNK(cur ^ 1);
            __syncthreads();
        }
    }

    float4 bb0 = *(const float4*)&b[n0 + tx * 8];
    float4 bb1 = *(const float4*)&b[n0 + tx * 8 + 4];
    float bias[8] = {bb0.x, bb0.y, bb0.z, bb0.w, bb1.x, bb1.y, bb1.z, bb1.w};
#pragma unroll
    for (int r = 0; r < 8; r++) {
        int m = m0 + ty * 8 + r;
        if (m < N_NODES) {
            float4 o0, o1;
            o0.x = acc[r][0] + bias[0];
            o0.y = acc[r][1] + bias[1];
            o0.z = acc[r][2] + bias[2];
            o0.w = acc[r][3] + bias[3];
            o1.x = acc[r][4] + bias[4];
            o1.y = acc[r][5] + bias[5];
            o1.z = acc[r][6] + bias[6];
            o1.w = acc[r][7] + bias[7];
            *(float4*)&out[m * F_OUT + n0 + tx * 8] = o0;
            *(float4*)&out[m * F_OUT + n0 + tx * 8 + 4] = o1;
        }
    }
}

// ---------------- launch ----------------
extern "C" void kernel_launch(void* const* d_in, const int* in_sizes, int n_in,
                              void* d_out, int out_size) {
    const float* x   = (const float*)d_in[0];
    const int*   src = (const int*)d_in[1];
    const int*   dst = (const int*)d_in[2];
    const float* W   = (const float*)d_in[3];
    const float* b   = (const float*)d_in[4];
    float* out = (float*)d_out;

    k_zero<<<(N_NODES + 255) / 256, 256>>>();
    k_deg<<<(N_EDGES / 4 + 255) / 256, 256>>>(dst);
    k_scan<<<1, 1024>>>();
    k_fill<<<(N_EDGES / 4 + 255) / 256, 256>>>(src, dst);
    k_gather<<<(N_NODES * 32 + 255) / 256, 256>>>(x);
    dim3 gg((N_NODES + BM - 1) / BM, F_OUT / BN);
    k_gemm<<<gg, 256>>>(W, b, out);
}

// round 6
// speedup vs baseline: 1.1135x; 1.0593x over previous
#include <cuda_runtime.h>
#include <cuda_bf16.h>
#include <cstdint>

#define N_NODES 10000
#define N_EDGES 640000
#define F_IN    128
#define F_OUT   512

// ---------------- device scratch ----------------
__device__ int   g_deg[N_NODES];
__device__ int   g_off[N_NODES + 1];
__device__ int   g_rank[N_EDGES];
__device__ int   g_csr[N_EDGES];
__device__ float g_h[N_NODES * F_IN];

// ---------------- 1. zero degree ----------------
__global__ void k_zero() {
    int i = blockIdx.x * blockDim.x + threadIdx.x;
    if (i < N_NODES) g_deg[i] = 0;
}

// ---------------- 2. count in-degree + record per-edge rank ----------------
__global__ void k_deg(const int* __restrict__ dst) {
    int t = blockIdx.x * blockDim.x + threadIdx.x;
    int e = t * 4;
    if (e < N_EDGES) {
        int4 d4 = *(const int4*)&dst[e];
        int r0 = atomicAdd(&g_deg[d4.x], 1);
        int r1 = atomicAdd(&g_deg[d4.y], 1);
        int r2 = atomicAdd(&g_deg[d4.z], 1);
        int r3 = atomicAdd(&g_deg[d4.w], 1);
        *(int4*)&g_rank[e] = make_int4(r0, r1, r2, r3);
    }
}

// ---------------- 3. exclusive scan (single block, warp shuffles) ----------------
__global__ void k_scan() {
    __shared__ int wsum[32];
    int t = threadIdx.x, lane = t & 31, wid = t >> 5;
    const int CH = 10;
    int base = t * CH;
    int loc[CH];
    int s = 0;
#pragma unroll
    for (int i = 0; i < CH; i++) {
        int idx = base + i;
        int v = (idx < N_NODES) ? g_deg[idx] : 0;
        loc[i] = s;
        s += v;
    }
    int inc = s;
#pragma unroll
    for (int o = 1; o < 32; o <<= 1) {
        int v = __shfl_up_sync(~0u, inc, o);
        if (lane >= o) inc += v;
    }
    if (lane == 31) wsum[wid] = inc;
    __syncthreads();
    if (wid == 0) {
        int sc = wsum[lane];
#pragma unroll
        for (int o = 1; o < 32; o <<= 1) {
            int u = __shfl_up_sync(~0u, sc, o);
            if (lane >= o) sc += u;
        }
        wsum[lane] = sc;
    }
    __syncthreads();
    int wex = (wid == 0) ? 0 : wsum[wid - 1];
    int excl = wex + inc - s;
#pragma unroll
    for (int i = 0; i < CH; i++) {
        int idx = base + i;
        if (idx < N_NODES) g_off[idx] = excl + loc[i];
    }
    if (t == 1023) g_off[N_NODES] = wsum[31];
}

// ---------------- 4. fill CSR (atomic-free), 2 edges/thread ----------------
__global__ void k_fill(const int* __restrict__ src, const int* __restrict__ dst) {
    int t = blockIdx.x * blockDim.x + threadIdx.x;
    int e = t * 2;
    if (e < N_EDGES) {
        int2 d2 = *(const int2*)&dst[e];
        int2 s2 = *(const int2*)&src[e];
        int2 r2 = *(const int2*)&g_rank[e];
        g_csr[g_off[d2.x] + r2.x] = s2.x;
        g_csr[g_off[d2.y] + r2.y] = s2.y;
    }
}

// ---------------- 5. gather-mean: one warp per destination node ----------------
__global__ void k_gather(const float* __restrict__ x) {
    int gw = (blockIdx.x * blockDim.x + threadIdx.x) >> 5;
    int lane = threadIdx.x & 31;
    if (gw >= N_NODES) return;

    const float4* __restrict__ x4 = (const float4*)x;
    int beg = g_off[gw];
    int end = g_off[gw + 1];

    float ax = 0.f, ay = 0.f, az = 0.f, aw = 0.f;
    int j = beg;
    for (; j + 7 < end; j += 8) {
        int s0 = g_csr[j + 0], s1 = g_csr[j + 1], s2 = g_csr[j + 2], s3 = g_csr[j + 3];
        int s4 = g_csr[j + 4], s5 = g_csr[j + 5], s6 = g_csr[j + 6], s7 = g_csr[j + 7];
        float4 v0 = x4[s0 * 32 + lane];
        float4 v1 = x4[s1 * 32 + lane];
        float4 v2 = x4[s2 * 32 + lane];
        float4 v3 = x4[s3 * 32 + lane];
        float4 v4 = x4[s4 * 32 + lane];
        float4 v5 = x4[s5 * 32 + lane];
        float4 v6 = x4[s6 * 32 + lane];
        float4 v7 = x4[s7 * 32 + lane];
        ax += ((v0.x + v1.x) + (v2.x + v3.x)) + ((v4.x + v5.x) + (v6.x + v7.x));
        ay += ((v0.y + v1.y) + (v2.y + v3.y)) + ((v4.y + v5.y) + (v6.y + v7.y));
        az += ((v0.z + v1.z) + (v2.z + v3.z)) + ((v4.z + v5.z) + (v6.z + v7.z));
        aw += ((v0.w + v1.w) + (v2.w + v3.w)) + ((v4.w + v5.w) + (v6.w + v7.w));
    }
    for (; j < end; ++j) {
        int s = g_csr[j];
        float4 v = x4[s * 32 + lane];
        ax += v.x; ay += v.y; az += v.z; aw += v.w;
    }

    int d = end - beg;
    float4 o;
    if (d > 0) {
        float inv = 1.0f / (float)d;
        o.x = ax * inv; o.y = ay * inv; o.z = az * inv; o.w = aw * inv;
    } else {
        o = x4[gw * 32 + lane];
    }
    ((float4*)g_h)[gw * 32 + lane] = o;
}

// ---------------- 6. mma.sync bf16 GEMM with exact hi/lo split ----------------
// out[N,512] = h[N,128] @ W[128,512] + b
// a = a_hi + a_lo (bf16); D = Ah*Bh + Ah*Bl + Al*Bh  (Al*Bl ~ 2^-18, dropped).
// Block 128x128, 8 warps, warp tile 32x64, mma.sync.m16n8k16.bf16.
#define GBM 128
#define GBN 128
#define APITCH 528
#define A_BYTES (128 * APITCH)
#define GEMM_SMEM_BYTES (2 * A_BYTES + 256)

__device__ __forceinline__ uint32_t smem_u32(const void* p) {
    uint32_t a;
    asm("{ .reg .u64 t; cvta.to.shared.u64 t, %1; cvt.u32.u64 %0, t; }"
        : "=r"(a) : "l"(p));
    return a;
}

#define LDMX4(r0, r1, r2, r3, addr)                                             \
    asm volatile("ldmatrix.sync.aligned.m8n8.x4.shared.b16 {%0,%1,%2,%3}, [%4];" \
                 : "=r"(r0), "=r"(r1), "=r"(r2), "=r"(r3) : "r"(addr))

#define MMA16816(c, a0, a1, a2, a3, b0, b1)                                     \
    asm volatile("mma.sync.aligned.m16n8k16.row.col.f32.bf16.bf16.f32 "         \
                 "{%0,%1,%2,%3}, {%4,%5,%6,%7}, {%8,%9}, {%0,%1,%2,%3};"        \
                 : "+f"((c)[0]), "+f"((c)[1]), "+f"((c)[2]), "+f"((c)[3])       \
                 : "r"(a0), "r"(a1), "r"(a2), "r"(a3), "r"(b0), "r"(b1))

__global__ void __launch_bounds__(256, 1)
k_gemm_mma(const float* __restrict__ W, const float* __restrict__ bias,
           float* __restrict__ out) {
    extern __shared__ char smem_raw[];
    uint32_t sb0 = smem_u32(smem_raw);
    uint32_t ab = (sb0 + 255) & ~255u;            // aligned base (smem u32 addr)
    char* tb = smem_raw + (ab - sb0);
    const uint32_t B_OFF = A_BYTES;

    int tid = threadIdx.x;
    int wid = tid >> 5, lane = tid & 31;
    int warp_m = wid & 3;        // 4 warps along M (32 rows each)
    int warp_n = wid >> 2;       // 2 warps along N (64 cols each)
    int m0 = blockIdx.x * GBM;
    int n0 = blockIdx.y * GBN;

    // ---- A tile: g_h rows -> bf16 hi/lo ----
    const float4* __restrict__ h4 = (const float4*)g_h;
    for (int i = tid; i < 128 * 32; i += 256) {
        int m = i >> 5;
        int kq = i & 31;             // float4 index (4 k values)
        float4 v = (m0 + m < N_NODES) ? h4[(size_t)(m0 + m) * 32 + kq]
                                      : make_float4(0.f, 0.f, 0.f, 0.f);
        __nv_bfloat16 h0 = __float2bfloat16(v.x);
        __nv_bfloat16 h1 = __float2bfloat16(v.y);
        __nv_bfloat16 h2 = __float2bfloat16(v.z);
        __nv_bfloat16 h3 = __float2bfloat16(v.w);
        __nv_bfloat16 l0 = __float2bfloat16(v.x - __bfloat162float(h0));
        __nv_bfloat16 l1 = __float2bfloat16(v.y - __bfloat162float(h1));
        __nv_bfloat16 l2 = __float2bfloat16(v.z - __bfloat162float(h2));
        __nv_bfloat16 l3 = __float2bfloat16(v.w - __bfloat162float(h3));
        uint2 hi = make_uint2(
            ((uint32_t)__bfloat16_as_ushort(h1) << 16) | __bfloat16_as_ushort(h0),
            ((uint32_t)__bfloat16_as_ushort(h3) << 16) | __bfloat16_as_ushort(h2));
        uint2 lo = make_uint2(
            ((uint32_t)__bfloat16_as_ushort(l1) << 16) | __bfloat16_as_ushort(l0),
            ((uint32_t)__bfloat16_as_ushort(l3) << 16) | __bfloat16_as_ushort(l2));
        char* row = tb + m * APITCH + kq * 8;
        *(uint2*)(row) = hi;
        *(uint2*)(row + 256) = lo;
    }

    // ---- B tile: Bs[n][k] = W[k][n0+n], hi/lo ----
    const float4* __restrict__ W4 = (const float4*)W;
    for (int i = tid; i < 128 * 32; i += 256) {
        int k = i >> 5;
        int nq = i & 31;             // 4 consecutive n
        float4 v = W4[(size_t)k * (F_OUT / 4) + (n0 >> 2) + nq];
        float vv[4] = {v.x, v.y, v.z, v.w};
#pragma unroll
        for (int j = 0; j < 4; j++) {
            int n = nq * 4 + j;
            __nv_bfloat16 bh = __float2bfloat16(vv[j]);
            __nv_bfloat16 bl = __float2bfloat16(vv[j] - __bfloat162float(bh));
            char* row = tb + B_OFF + n * APITCH + k * 2;
            *(unsigned short*)(row) = __bfloat16_as_ushort(bh);
            *(unsigned short*)(row + 256) = __bfloat16_as_ushort(bl);
        }
    }
    __syncthreads();

    float acc[2][8][4] = {};

    // A ldmatrix lane address pieces
    int a_row = (lane & 15);             // row within m16 tile
    int a_koff = (lane >> 4) << 4;       // 0 or 16 bytes (k 0-7 vs 8-15)
    // B ldmatrix lane pieces (two n8 tiles per x4)
    int b_nrow = ((lane >> 4) << 3) + (lane & 7);  // n within 16-row group
    int b_koff = ((lane >> 3) & 1) << 4;           // 0 or 16 bytes

    // virtual K = 384: pass 0 Ah*Bh, pass 1 Ah*Bl, pass 2 Al*Bh
#pragma unroll
    for (int pass = 0; pass < 3; pass++) {
        uint32_t abase = (pass < 2) ? 0u : 256u;        // Ah or Al
        uint32_t bbase = (pass == 1) ? 256u : 0u;       // Bh or Bl
#pragma unroll
        for (int kk = 0; kk < 8; kk++) {
            uint32_t kb = kk * 32;       // 16 k-values = 32 bytes per MMA step
            // A fragments: 2 m16 tiles
            uint32_t a0, a1, a2, a3, a4, a5, a6, a7;
            {
                uint32_t addr0 = ab + (uint32_t)((warp_m * 32 + a_row) * APITCH) +
                                 abase + kb + a_koff;
                uint32_t addr1 = addr0 + 16 * APITCH;
                LDMX4(a0, a1, a2, a3, addr0);
                LDMX4(a4, a5, a6, a7, addr1);
            }
            // B fragments: 8 n8 tiles, loaded 2 at a time
#pragma unroll
            for (int nt2 = 0; nt2 < 4; nt2++) {
                uint32_t baddr = ab + B_OFF +
                                 (uint32_t)((warp_n * 64 + nt2 * 16 + b_nrow) * APITCH) +
                                 bbase + kb + b_koff;
                uint32_t b0, b1, b2, b3;
                LDMX4(b0, b1, b2, b3, baddr);
                MMA16816(acc[0][nt2 * 2 + 0], a0, a1, a2, a3, b0, b1);
                MMA16816(acc[1][nt2 * 2 + 0], a4, a5, a6, a7, b0, b1);
                MMA16816(acc[0][nt2 * 2 + 1], a0, a1, a2, a3, b2, b3);
                MMA16816(acc[1][nt2 * 2 + 1], a4, a5, a6, a7, b2, b3);
            }
        }
    }

    // ---- epilogue: C frag -> gmem + bias ----
    int g = lane >> 2;          // row within m8 group
    int t = lane & 3;           // col pair index
#pragma unroll
    for (int mt = 0; mt < 2; mt++) {
        int row0 = m0 + warp_m * 32 + mt * 16 + g;
        int row1 = row0 + 8;
#pragma unroll
        for (int nt = 0; nt < 8; nt++) {
            int col = n0 + warp_n * 64 + nt * 8 + t * 2;
            float2 bv = *(const float2*)&bias[col];
            if (row0 < N_NODES) {
                float2 o = make_float2(acc[mt][nt][0] + bv.x, acc[mt][nt][1] + bv.y);
                *(float2*)&out[(size_t)row0 * F_OUT + col] = o;
            }
            if (row1 < N_NODES) {
                float2 o = make_float2(acc[mt][nt][2] + bv.x, acc[mt][nt][3] + bv.y);
                *(float2*)&out[(size_t)row1 * F_OUT + col] = o;
            }
        }
    }
}

// ---------------- launch ----------------
extern "C" void kernel_launch(void* const* d_in, const int* in_sizes, int n_in,
                              void* d_out, int out_size) {
    const float* x   = (const float*)d_in[0];
    const int*   src = (const int*)d_in[1];
    const int*   dst = (const int*)d_in[2];
    const float* W   = (const float*)d_in[3];
    const float* b   = (const float*)d_in[4];
    float* out = (float*)d_out;

    cudaFuncSetAttribute(k_gemm_mma, cudaFuncAttributeMaxDynamicSharedMemorySize,
                         GEMM_SMEM_BYTES);

    k_zero<<<(N_NODES + 255) / 256, 256>>>();
    k_deg<<<(N_EDGES / 4 + 255) / 256, 256>>>(dst);
    k_scan<<<1, 1024>>>();
    k_fill<<<(N_EDGES / 2 + 255) / 256, 256>>>(src, dst);
    k_gather<<<(N_NODES * 32 + 255) / 256, 256>>>(x);
    dim3 gg((N_NODES + GBM - 1) / GBM, F_OUT / GBN);
    k_gemm_mma<<<gg, 256, GEMM_SMEM_BYTES>>>(W, b, out);
}

// round 7
// speedup vs baseline: 1.4748x; 1.3245x over previous
#include <cuda_runtime.h>
#include <cuda_bf16.h>
#include <cstdint>

#define N_NODES 10000
#define N_EDGES 640000
#define F_IN    128
#define F_OUT   512

// ---------------- device scratch ----------------
__device__ int   g_deg[N_NODES];
__device__ int   g_off[N_NODES + 1];
__device__ int   g_rank[N_EDGES];
__device__ int   g_csr[N_EDGES];
// h as packed bf16 hi/lo rows (128 bf16 = 256B per row)
__device__ __align__(16) unsigned short g_hh[N_NODES * F_IN];
__device__ __align__(16) unsigned short g_hl[N_NODES * F_IN];
// W transposed to [n][k], bf16 hi/lo
__device__ __align__(16) unsigned short g_wt_hi[F_OUT * F_IN];
__device__ __align__(16) unsigned short g_wt_lo[F_OUT * F_IN];

__device__ __forceinline__ void split_bf16(float v, unsigned short& h, unsigned short& l) {
    __nv_bfloat16 bh = __float2bfloat16(v);
    __nv_bfloat16 bl = __float2bfloat16(v - __bfloat162float(bh));
    h = __bfloat16_as_ushort(bh);
    l = __bfloat16_as_ushort(bl);
}

// ---------------- W transpose + bf16 split (one-time per launch) -------------
__global__ void k_wconv(const float* __restrict__ W) {
    int idx = blockIdx.x * blockDim.x + threadIdx.x;   // idx = n*128 + k
    if (idx < F_OUT * F_IN) {
        int n = idx >> 7, k = idx & 127;
        float v = W[(size_t)k * F_OUT + n];
        unsigned short h, l;
        split_bf16(v, h, l);
        g_wt_hi[idx] = h;
        g_wt_lo[idx] = l;
    }
}

// ---------------- count in-degree + record per-edge rank (8 edges/thread) ----
__global__ void k_deg(const int* __restrict__ dst) {
    int t = blockIdx.x * blockDim.x + threadIdx.x;
    int e = t * 8;
    if (e < N_EDGES) {
        int4 a = *(const int4*)&dst[e];
        int4 b = *(const int4*)&dst[e + 4];
        int r0 = atomicAdd(&g_deg[a.x], 1);
        int r1 = atomicAdd(&g_deg[a.y], 1);
        int r2 = atomicAdd(&g_deg[a.z], 1);
        int r3 = atomicAdd(&g_deg[a.w], 1);
        int r4 = atomicAdd(&g_deg[b.x], 1);
        int r5 = atomicAdd(&g_deg[b.y], 1);
        int r6 = atomicAdd(&g_deg[b.z], 1);
        int r7 = atomicAdd(&g_deg[b.w], 1);
        *(int4*)&g_rank[e]     = make_int4(r0, r1, r2, r3);
        *(int4*)&g_rank[e + 4] = make_int4(r4, r5, r6, r7);
    }
}

// ---------------- exclusive scan (single block, warp shuffles) ---------------
__global__ void k_scan() {
    __shared__ int wsum[32];
    int t = threadIdx.x, lane = t & 31, wid = t >> 5;
    const int CH = 10;
    int base = t * CH;
    int loc[CH];
    int s = 0;
#pragma unroll
    for (int i = 0; i < CH; i++) {
        int idx = base + i;
        int v = (idx < N_NODES) ? g_deg[idx] : 0;
        loc[i] = s;
        s += v;
    }
    int inc = s;
#pragma unroll
    for (int o = 1; o < 32; o <<= 1) {
        int v = __shfl_up_sync(~0u, inc, o);
        if (lane >= o) inc += v;
    }
    if (lane == 31) wsum[wid] = inc;
    __syncthreads();
    if (wid == 0) {
        int sc = wsum[lane];
#pragma unroll
        for (int o = 1; o < 32; o <<= 1) {
            int u = __shfl_up_sync(~0u, sc, o);
            if (lane >= o) sc += u;
        }
        wsum[lane] = sc;
    }
    __syncthreads();
    int wex = (wid == 0) ? 0 : wsum[wid - 1];
    int excl = wex + inc - s;
#pragma unroll
    for (int i = 0; i < CH; i++) {
        int idx = base + i;
        if (idx < N_NODES) g_off[idx] = excl + loc[i];
    }
    if (t == 1023) g_off[N_NODES] = wsum[31];
}

// ---------------- fill CSR (atomic-free), 4 edges/thread ---------------------
__global__ void k_fill(const int* __restrict__ src, const int* __restrict__ dst) {
    int t = blockIdx.x * blockDim.x + threadIdx.x;
    int e = t * 4;
    if (e < N_EDGES) {
        int4 d4 = *(const int4*)&dst[e];
        int4 s4 = *(const int4*)&src[e];
        int4 r4 = *(const int4*)&g_rank[e];
        int o0 = g_off[d4.x], o1 = g_off[d4.y], o2 = g_off[d4.z], o3 = g_off[d4.w];
        g_csr[o0 + r4.x] = s4.x;
        g_csr[o1 + r4.y] = s4.y;
        g_csr[o2 + r4.z] = s4.z;
        g_csr[o3 + r4.w] = s4.w;
    }
}

// ---------------- gather-mean -> bf16 hi/lo rows (warp per node) -------------
__global__ void k_gather(const float* __restrict__ x) {
    int gw = (blockIdx.x * blockDim.x + threadIdx.x) >> 5;
    int lane = threadIdx.x & 31;
    if (gw >= N_NODES) return;

    const float4* __restrict__ x4 = (const float4*)x;
    int beg = g_off[gw];
    int end = g_off[gw + 1];

    float ax = 0.f, ay = 0.f, az = 0.f, aw = 0.f;
    int j = beg;
    for (; j + 7 < end; j += 8) {
        int s0 = g_csr[j + 0], s1 = g_csr[j + 1], s2 = g_csr[j + 2], s3 = g_csr[j + 3];
        int s4 = g_csr[j + 4], s5 = g_csr[j + 5], s6 = g_csr[j + 6], s7 = g_csr[j + 7];
        float4 v0 = x4[s0 * 32 + lane];
        float4 v1 = x4[s1 * 32 + lane];
        float4 v2 = x4[s2 * 32 + lane];
        float4 v3 = x4[s3 * 32 + lane];
        float4 v4 = x4[s4 * 32 + lane];
        float4 v5 = x4[s5 * 32 + lane];
        float4 v6 = x4[s6 * 32 + lane];
        float4 v7 = x4[s7 * 32 + lane];
        ax += ((v0.x + v1.x) + (v2.x + v3.x)) + ((v4.x + v5.x) + (v6.x + v7.x));
        ay += ((v0.y + v1.y) + (v2.y + v3.y)) + ((v4.y + v5.y) + (v6.y + v7.y));
        az += ((v0.z + v1.z) + (v2.z + v3.z)) + ((v4.z + v5.z) + (v6.z + v7.z));
        aw += ((v0.w + v1.w) + (v2.w + v3.w)) + ((v4.w + v5.w) + (v6.w + v7.w));
    }
    for (; j < end; ++j) {
        int s = g_csr[j];
        float4 v = x4[s * 32 + lane];
        ax += v.x; ay += v.y; az += v.z; aw += v.w;
    }

    int d = end - beg;
    float4 o;
    if (d > 0) {
        float inv = 1.0f / (float)d;
        o.x = ax * inv; o.y = ay * inv; o.z = az * inv; o.w = aw * inv;
    } else {
        o = x4[gw * 32 + lane];
    }

    // convert to bf16 hi/lo and store packed (8B per lane per array)
    unsigned short h0, h1, h2, h3, l0, l1, l2, l3;
    split_bf16(o.x, h0, l0);
    split_bf16(o.y, h1, l1);
    split_bf16(o.z, h2, l2);
    split_bf16(o.w, h3, l3);
    uint2 hv = make_uint2(((uint32_t)h1 << 16) | h0, ((uint32_t)h3 << 16) | h2);
    uint2 lv = make_uint2(((uint32_t)l1 << 16) | l0, ((uint32_t)l3 << 16) | l2);
    int base = gw * F_IN + lane * 4;
    *(uint2*)&g_hh[base] = hv;
    *(uint2*)&g_hl[base] = lv;
}

// ---------------- mma.sync bf16 GEMM (inputs pre-split) ----------------------
// out[N,512] = h[N,128] @ W[128,512] + b ; D = Ah*Bh + Ah*Bl + Al*Bh
// Block 128x128, 8 warps, warp tile 32x64, mma.sync.m16n8k16.bf16.
#define GBM 128
#define GBN 128
#define APITCH 528
#define A_BYTES (128 * APITCH)
#define GEMM_SMEM_BYTES (2 * A_BYTES + 256)

__device__ __forceinline__ uint32_t smem_u32(const void* p) {
    uint32_t a;
    asm("{ .reg .u64 t; cvta.to.shared.u64 t, %1; cvt.u32.u64 %0, t; }"
        : "=r"(a) : "l"(p));
    return a;
}

#define LDMX4(r0, r1, r2, r3, addr)                                             \
    asm volatile("ldmatrix.sync.aligned.m8n8.x4.shared.b16 {%0,%1,%2,%3}, [%4];" \
                 : "=r"(r0), "=r"(r1), "=r"(r2), "=r"(r3) : "r"(addr))

#define MMA16816(c, a0, a1, a2, a3, b0, b1)                                     \
    asm volatile("mma.sync.aligned.m16n8k16.row.col.f32.bf16.bf16.f32 "         \
                 "{%0,%1,%2,%3}, {%4,%5,%6,%7}, {%8,%9}, {%0,%1,%2,%3};"        \
                 : "+f"((c)[0]), "+f"((c)[1]), "+f"((c)[2]), "+f"((c)[3])       \
                 : "r"(a0), "r"(a1), "r"(a2), "r"(a3), "r"(b0), "r"(b1))

__global__ void __launch_bounds__(256, 1)
k_gemm_mma(const float* __restrict__ bias, float* __restrict__ out) {
    extern __shared__ char smem_raw[];
    uint32_t sb0 = smem_u32(smem_raw);
    uint32_t ab = (sb0 + 255) & ~255u;
    char* tb = smem_raw + (ab - sb0);
    const uint32_t B_OFF = A_BYTES;

    int tid = threadIdx.x;
    int wid = tid >> 5, lane = tid & 31;
    int warp_m = wid & 3;
    int warp_n = wid >> 2;
    int m0 = blockIdx.x * GBM;
    int n0 = blockIdx.y * GBN;

    // ---- A tile: copy pre-split bf16 rows (16B chunks) ----
    const uint4* __restrict__ hh4 = (const uint4*)g_hh;
    const uint4* __restrict__ hl4 = (const uint4*)g_hl;
    for (int i = tid; i < 128 * 16; i += 256) {
        int m = i >> 4;
        int c = i & 15;                   // 16B chunk within 256B row
        uint4 hv, lv;
        if (m0 + m < N_NODES) {
            hv = hh4[(size_t)(m0 + m) * 16 + c];
            lv = hl4[(size_t)(m0 + m) * 16 + c];
        } else {
            hv = make_uint4(0, 0, 0, 0);
            lv = make_uint4(0, 0, 0, 0);
        }
        char* row = tb + m * APITCH + c * 16;
        *(uint4*)(row) = hv;
        *(uint4*)(row + 256) = lv;
    }

    // ---- B tile: copy pre-transposed W bf16 rows ----
    const uint4* __restrict__ wh4 = (const uint4*)g_wt_hi;
    const uint4* __restrict__ wl4 = (const uint4*)g_wt_lo;
    for (int i = tid; i < 128 * 16; i += 256) {
        int n = i >> 4;
        int c = i & 15;
        uint4 hv = wh4[(size_t)(n0 + n) * 16 + c];
        uint4 lv = wl4[(size_t)(n0 + n) * 16 + c];
        char* row = tb + B_OFF + n * APITCH + c * 16;
        *(uint4*)(row) = hv;
        *(uint4*)(row + 256) = lv;
    }
    __syncthreads();

    float acc[2][8][4] = {};

    int a_row = (lane & 15);
    int a_koff = (lane >> 4) << 4;
    int b_nrow = ((lane >> 4) << 3) + (lane & 7);
    int b_koff = ((lane >> 3) & 1) << 4;

#pragma unroll
    for (int pass = 0; pass < 3; pass++) {
        uint32_t abase = (pass < 2) ? 0u : 256u;
        uint32_t bbase = (pass == 1) ? 256u : 0u;
#pragma unroll
        for (int kk = 0; kk < 8; kk++) {
            uint32_t kb = kk * 32;
            uint32_t a0, a1, a2, a3, a4, a5, a6, a7;
            {
                uint32_t addr0 = ab + (uint32_t)((warp_m * 32 + a_row) * APITCH) +
                                 abase + kb + a_koff;
                uint32_t addr1 = addr0 + 16 * APITCH;
                LDMX4(a0, a1, a2, a3, addr0);
                LDMX4(a4, a5, a6, a7, addr1);
            }
#pragma unroll
            for (int nt2 = 0; nt2 < 4; nt2++) {
                uint32_t baddr = ab + B_OFF +
                                 (uint32_t)((warp_n * 64 + nt2 * 16 + b_nrow) * APITCH) +
                                 bbase + kb + b_koff;
                uint32_t b0, b1, b2, b3;
                LDMX4(b0, b1, b2, b3, baddr);
                MMA16816(acc[0][nt2 * 2 + 0], a0, a1, a2, a3, b0, b1);
                MMA16816(acc[1][nt2 * 2 + 0], a4, a5, a6, a7, b0, b1);
                MMA16816(acc[0][nt2 * 2 + 1], a0, a1, a2, a3, b2, b3);
                MMA16816(acc[1][nt2 * 2 + 1], a4, a5, a6, a7, b2, b3);
            }
        }
    }

    // ---- epilogue ----
    int g = lane >> 2;
    int t = lane & 3;
#pragma unroll
    for (int mt = 0; mt < 2; mt++) {
        int row0 = m0 + warp_m * 32 + mt * 16 + g;
        int row1 = row0 + 8;
#pragma unroll
        for (int nt = 0; nt < 8; nt++) {
            int col = n0 + warp_n * 64 + nt * 8 + t * 2;
            float2 bv = *(const float2*)&bias[col];
            if (row0 < N_NODES) {
                float2 o = make_float2(acc[mt][nt][0] + bv.x, acc[mt][nt][1] + bv.y);
                *(float2*)&out[(size_t)row0 * F_OUT + col] = o;
            }
            if (row1 < N_NODES) {
                float2 o = make_float2(acc[mt][nt][2] + bv.x, acc[mt][nt][3] + bv.y);
                *(float2*)&out[(size_t)row1 * F_OUT + col] = o;
            }
        }
    }
}

// ---------------- launch ----------------
extern "C" void kernel_launch(void* const* d_in, const int* in_sizes, int n_in,
                              void* d_out, int out_size) {
    const float* x   = (const float*)d_in[0];
    const int*   src = (const int*)d_in[1];
    const int*   dst = (const int*)d_in[2];
    const float* W   = (const float*)d_in[3];
    const float* b   = (const float*)d_in[4];
    float* out = (float*)d_out;

    cudaFuncSetAttribute(k_gemm_mma, cudaFuncAttributeMaxDynamicSharedMemorySize,
                         GEMM_SMEM_BYTES);

    void* degp = nullptr;
    cudaGetSymbolAddress(&degp, g_deg);
    cudaMemsetAsync(degp, 0, N_NODES * sizeof(int));

    k_wconv<<<(F_OUT * F_IN + 255) / 256, 256>>>(W);
    k_deg<<<(N_EDGES / 8 + 255) / 256, 256>>>(dst);
    k_scan<<<1, 1024>>>();
    k_fill<<<(N_EDGES / 4 + 255) / 256, 256>>>(src, dst);
    k_gather<<<(N_NODES * 32 + 255) / 256, 256>>>(x);
    dim3 gg((N_NODES + GBM - 1) / GBM, F_OUT / GBN);
    k_gemm_mma<<<gg, 256, GEMM_SMEM_BYTES>>>(b, out);
}

// round 8
// speedup vs baseline: 1.5132x; 1.0260x over previous
#include <cuda_runtime.h>
#include <cuda_bf16.h>
#include <cuda_fp16.h>
#include <cstdint>

#define N_NODES 10000
#define N_EDGES 640000
#define F_IN    128
#define F_OUT   512

// ---------------- device scratch ----------------
__device__ int   g_deg[N_NODES];
__device__ int   g_off[N_NODES + 1];
__device__ int   g_rank[N_EDGES];
__device__ int   g_csr[N_EDGES];
// x converted to fp16 (row-major, 128 per row)
__device__ __align__(16) __half g_x16[N_NODES * F_IN];
// h as packed bf16 hi/lo rows (128 bf16 = 256B per row)
__device__ __align__(16) unsigned short g_hh[N_NODES * F_IN];
__device__ __align__(16) unsigned short g_hl[N_NODES * F_IN];
// W transposed to [n][k], bf16 hi/lo
__device__ __align__(16) unsigned short g_wt_hi[F_OUT * F_IN];
__device__ __align__(16) unsigned short g_wt_lo[F_OUT * F_IN];

__device__ __forceinline__ void split_bf16(float v, unsigned short& h, unsigned short& l) {
    __nv_bfloat16 bh = __float2bfloat16(v);
    __nv_bfloat16 bl = __float2bfloat16(v - __bfloat162float(bh));
    h = __bfloat16_as_ushort(bh);
    l = __bfloat16_as_ushort(bl);
}

// ---------------- x -> fp16 conversion ----------------
__global__ void k_xconv(const float* __restrict__ x) {
    int i = blockIdx.x * blockDim.x + threadIdx.x;   // one float4 per thread
    if (i < N_NODES * F_IN / 4) {
        float4 v = ((const float4*)x)[i];
        __half2 a = __floats2half2_rn(v.x, v.y);
        __half2 b = __floats2half2_rn(v.z, v.w);
        ((uint2*)g_x16)[i] = make_uint2(*(uint32_t*)&a, *(uint32_t*)&b);
    }
}

// ---------------- W transpose + bf16 split ----------------
__global__ void k_wconv(const float* __restrict__ W) {
    int idx = blockIdx.x * blockDim.x + threadIdx.x;   // idx = n*128 + k
    if (idx < F_OUT * F_IN) {
        int n = idx >> 7, k = idx & 127;
        float v = W[(size_t)k * F_OUT + n];
        unsigned short h, l;
        split_bf16(v, h, l);
        g_wt_hi[idx] = h;
        g_wt_lo[idx] = l;
    }
}

// ---------------- count in-degree + record per-edge rank (8 edges/thread) ----
__global__ void k_deg(const int* __restrict__ dst) {
    int t = blockIdx.x * blockDim.x + threadIdx.x;
    int e = t * 8;
    if (e < N_EDGES) {
        int4 a = *(const int4*)&dst[e];
        int4 b = *(const int4*)&dst[e + 4];
        int r0 = atomicAdd(&g_deg[a.x], 1);
        int r1 = atomicAdd(&g_deg[a.y], 1);
        int r2 = atomicAdd(&g_deg[a.z], 1);
        int r3 = atomicAdd(&g_deg[a.w], 1);
        int r4 = atomicAdd(&g_deg[b.x], 1);
        int r5 = atomicAdd(&g_deg[b.y], 1);
        int r6 = atomicAdd(&g_deg[b.z], 1);
        int r7 = atomicAdd(&g_deg[b.w], 1);
        *(int4*)&g_rank[e]     = make_int4(r0, r1, r2, r3);
        *(int4*)&g_rank[e + 4] = make_int4(r4, r5, r6, r7);
    }
}

// ---------------- exclusive scan (single block, warp shuffles) ---------------
__global__ void k_scan() {
    __shared__ int wsum[32];
    int t = threadIdx.x, lane = t & 31, wid = t >> 5;
    const int CH = 10;
    int base = t * CH;
    int loc[CH];
    int s = 0;
#pragma unroll
    for (int i = 0; i < CH; i++) {
        int idx = base + i;
        int v = (idx < N_NODES) ? g_deg[idx] : 0;
        loc[i] = s;
        s += v;
    }
    int inc = s;
#pragma unroll
    for (int o = 1; o < 32; o <<= 1) {
        int v = __shfl_up_sync(~0u, inc, o);
        if (lane >= o) inc += v;
    }
    if (lane == 31) wsum[wid] = inc;
    __syncthreads();
    if (wid == 0) {
        int sc = wsum[lane];
#pragma unroll
        for (int o = 1; o < 32; o <<= 1) {
            int u = __shfl_up_sync(~0u, sc, o);
            if (lane >= o) sc += u;
        }
        wsum[lane] = sc;
    }
    __syncthreads();
    int wex = (wid == 0) ? 0 : wsum[wid - 1];
    int excl = wex + inc - s;
#pragma unroll
    for (int i = 0; i < CH; i++) {
        int idx = base + i;
        if (idx < N_NODES) g_off[idx] = excl + loc[i];
    }
    if (t == 1023) g_off[N_NODES] = wsum[31];
}

// ---------------- fill CSR (atomic-free), 4 edges/thread ---------------------
__global__ void k_fill(const int* __restrict__ src, const int* __restrict__ dst) {
    int t = blockIdx.x * blockDim.x + threadIdx.x;
    int e = t * 4;
    if (e < N_EDGES) {
        int4 d4 = *(const int4*)&dst[e];
        int4 s4 = *(const int4*)&src[e];
        int4 r4 = *(const int4*)&g_rank[e];
        int o0 = g_off[d4.x], o1 = g_off[d4.y], o2 = g_off[d4.z], o3 = g_off[d4.w];
        g_csr[o0 + r4.x] = s4.x;
        g_csr[o1 + r4.y] = s4.y;
        g_csr[o2 + r4.z] = s4.z;
        g_csr[o3 + r4.w] = s4.w;
    }
}

// ---------------- gather-mean (fp16 reads) -> bf16 hi/lo rows ----------------
// warp per node; lane owns features [4*lane, 4*lane+4) = one uint2 of half2s.
__global__ void k_gather(const float* __restrict__ x) {
    int gw = (blockIdx.x * blockDim.x + threadIdx.x) >> 5;
    int lane = threadIdx.x & 31;
    if (gw >= N_NODES) return;

    const uint2* __restrict__ x2 = (const uint2*)g_x16;   // 32 uint2 per row
    int beg = g_off[gw];
    int end = g_off[gw + 1];

    float ax = 0.f, ay = 0.f, az = 0.f, aw = 0.f;
    int j = beg;
    for (; j + 7 < end; j += 8) {
        int s0 = g_csr[j + 0], s1 = g_csr[j + 1], s2 = g_csr[j + 2], s3 = g_csr[j + 3];
        int s4 = g_csr[j + 4], s5 = g_csr[j + 5], s6 = g_csr[j + 6], s7 = g_csr[j + 7];
        uint2 c0 = x2[s0 * 32 + lane];
        uint2 c1 = x2[s1 * 32 + lane];
        uint2 c2 = x2[s2 * 32 + lane];
        uint2 c3 = x2[s3 * 32 + lane];
        uint2 c4 = x2[s4 * 32 + lane];
        uint2 c5 = x2[s5 * 32 + lane];
        uint2 c6 = x2[s6 * 32 + lane];
        uint2 c7 = x2[s7 * 32 + lane];
#define ACC(c)                                                     \
        {                                                          \
            float2 f0 = __half22float2(*(__half2*)&(c).x);         \
            float2 f1 = __half22float2(*(__half2*)&(c).y);         \
            ax += f0.x; ay += f0.y; az += f1.x; aw += f1.y;        \
        }
        ACC(c0) ACC(c1) ACC(c2) ACC(c3) ACC(c4) ACC(c5) ACC(c6) ACC(c7)
    }
    for (; j < end; ++j) {
        int s = g_csr[j];
        uint2 c = x2[s * 32 + lane];
        ACC(c)
    }
#undef ACC

    int d = end - beg;
    float4 o;
    if (d > 0) {
        float inv = 1.0f / (float)d;
        o.x = ax * inv; o.y = ay * inv; o.z = az * inv; o.w = aw * inv;
    } else {
        // zero-in-degree: keep EXACT fp32 inputs
        o = ((const float4*)x)[gw * 32 + lane];
    }

    unsigned short h0, h1, h2, h3, l0, l1, l2, l3;
    split_bf16(o.x, h0, l0);
    split_bf16(o.y, h1, l1);
    split_bf16(o.z, h2, l2);
    split_bf16(o.w, h3, l3);
    uint2 hv = make_uint2(((uint32_t)h1 << 16) | h0, ((uint32_t)h3 << 16) | h2);
    uint2 lv = make_uint2(((uint32_t)l1 << 16) | l0, ((uint32_t)l3 << 16) | l2);
    int base = gw * F_IN + lane * 4;
    *(uint2*)&g_hh[base] = hv;
    *(uint2*)&g_hl[base] = lv;
}

// ---------------- mma.sync bf16 GEMM (inputs pre-split) ----------------------
#define GBM 128
#define GBN 128
#define APITCH 528
#define A_BYTES (128 * APITCH)
#define GEMM_SMEM_BYTES (2 * A_BYTES + 256)

__device__ __forceinline__ uint32_t smem_u32(const void* p) {
    uint32_t a;
    asm("{ .reg .u64 t; cvta.to.shared.u64 t, %1; cvt.u32.u64 %0, t; }"
        : "=r"(a) : "l"(p));
    return a;
}

#define LDMX4(r0, r1, r2, r3, addr)                                             \
    asm volatile("ldmatrix.sync.aligned.m8n8.x4.shared.b16 {%0,%1,%2,%3}, [%4];" \
                 : "=r"(r0), "=r"(r1), "=r"(r2), "=r"(r3) : "r"(addr))

#define MMA16816(c, a0, a1, a2, a3, b0, b1)                                     \
    asm volatile("mma.sync.aligned.m16n8k16.row.col.f32.bf16.bf16.f32 "         \
                 "{%0,%1,%2,%3}, {%4,%5,%6,%7}, {%8,%9}, {%0,%1,%2,%3};"        \
                 : "+f"((c)[0]), "+f"((c)[1]), "+f"((c)[2]), "+f"((c)[3])       \
                 : "r"(a0), "r"(a1), "r"(a2), "r"(a3), "r"(b0), "r"(b1))

__global__ void __launch_bounds__(256, 1)
k_gemm_mma(const float* __restrict__ bias, float* __restrict__ out) {
    extern __shared__ char smem_raw[];
    uint32_t sb0 = smem_u32(smem_raw);
    uint32_t ab = (sb0 + 255) & ~255u;
    char* tb = smem_raw + (ab - sb0);
    const uint32_t B_OFF = A_BYTES;

    int tid = threadIdx.x;
    int wid = tid >> 5, lane = tid & 31;
    int warp_m = wid & 3;
    int warp_n = wid >> 2;
    int m0 = blockIdx.x * GBM;
    int n0 = blockIdx.y * GBN;

    const uint4* __restrict__ hh4 = (const uint4*)g_hh;
    const uint4* __restrict__ hl4 = (const uint4*)g_hl;
    for (int i = tid; i < 128 * 16; i += 256) {
        int m = i >> 4;
        int c = i & 15;
        uint4 hv, lv;
        if (m0 + m < N_NODES) {
            hv = hh4[(size_t)(m0 + m) * 16 + c];
            lv = hl4[(size_t)(m0 + m) * 16 + c];
        } else {
            hv = make_uint4(0, 0, 0, 0);
            lv = make_uint4(0, 0, 0, 0);
        }
        char* row = tb + m * APITCH + c * 16;
        *(uint4*)(row) = hv;
        *(uint4*)(row + 256) = lv;
    }

    const uint4* __restrict__ wh4 = (const uint4*)g_wt_hi;
    const uint4* __restrict__ wl4 = (const uint4*)g_wt_lo;
    for (int i = tid; i < 128 * 16; i += 256) {
        int n = i >> 4;
        int c = i & 15;
        uint4 hv = wh4[(size_t)(n0 + n) * 16 + c];
        uint4 lv = wl4[(size_t)(n0 + n) * 16 + c];
        char* row = tb + B_OFF + n * APITCH + c * 16;
        *(uint4*)(row) = hv;
        *(uint4*)(row + 256) = lv;
    }
    __syncthreads();

    float acc[2][8][4] = {};

    int a_row = (lane & 15);
    int a_koff = (lane >> 4) << 4;
    int b_nrow = ((lane >> 4) << 3) + (lane & 7);
    int b_koff = ((lane >> 3) & 1) << 4;

#pragma unroll
    for (int pass = 0; pass < 3; pass++) {
        uint32_t abase = (pass < 2) ? 0u : 256u;
        uint32_t bbase = (pass == 1) ? 256u : 0u;
#pragma unroll
        for (int kk = 0; kk < 8; kk++) {
            uint32_t kb = kk * 32;
            uint32_t a0, a1, a2, a3, a4, a5, a6, a7;
            {
                uint32_t addr0 = ab + (uint32_t)((warp_m * 32 + a_row) * APITCH) +
                                 abase + kb + a_koff;
                uint32_t addr1 = addr0 + 16 * APITCH;
                LDMX4(a0, a1, a2, a3, addr0);
                LDMX4(a4, a5, a6, a7, addr1);
            }
#pragma unroll
            for (int nt2 = 0; nt2 < 4; nt2++) {
                uint32_t baddr = ab + B_OFF +
                                 (uint32_t)((warp_n * 64 + nt2 * 16 + b_nrow) * APITCH) +
                                 bbase + kb + b_koff;
                uint32_t b0, b1, b2, b3;
                LDMX4(b0, b1, b2, b3, baddr);
                MMA16816(acc[0][nt2 * 2 + 0], a0, a1, a2, a3, b0, b1);
                MMA16816(acc[1][nt2 * 2 + 0], a4, a5, a6, a7, b0, b1);
                MMA16816(acc[0][nt2 * 2 + 1], a0, a1, a2, a3, b2, b3);
                MMA16816(acc[1][nt2 * 2 + 1], a4, a5, a6, a7, b2, b3);
            }
        }
    }

    int g = lane >> 2;
    int t = lane & 3;
#pragma unroll
    for (int mt = 0; mt < 2; mt++) {
        int row0 = m0 + warp_m * 32 + mt * 16 + g;
        int row1 = row0 + 8;
#pragma unroll
        for (int nt = 0; nt < 8; nt++) {
            int col = n0 + warp_n * 64 + nt * 8 + t * 2;
            float2 bv = *(const float2*)&bias[col];
            if (row0 < N_NODES) {
                float2 o = make_float2(acc[mt][nt][0] + bv.x, acc[mt][nt][1] + bv.y);
                *(float2*)&out[(size_t)row0 * F_OUT + col] = o;
            }
            if (row1 < N_NODES) {
                float2 o = make_float2(acc[mt][nt][2] + bv.x, acc[mt][nt][3] + bv.y);
                *(float2*)&out[(size_t)row1 * F_OUT + col] = o;
            }
        }
    }
}

// ---------------- launch ----------------
extern "C" void kernel_launch(void* const* d_in, const int* in_sizes, int n_in,
                              void* d_out, int out_size) {
    const float* x   = (const float*)d_in[0];
    const int*   src = (const int*)d_in[1];
    const int*   dst = (const int*)d_in[2];
    const float* W   = (const float*)d_in[3];
    const float* b   = (const float*)d_in[4];
    float* out = (float*)d_out;

    cudaFuncSetAttribute(k_gemm_mma, cudaFuncAttributeMaxDynamicSharedMemorySize,
                         GEMM_SMEM_BYTES);

    void* degp = nullptr;
    cudaGetSymbolAddress(&degp, g_deg);
    cudaMemsetAsync(degp, 0, N_NODES * sizeof(int));

    k_xconv<<<(N_NODES * F_IN / 4 + 255) / 256, 256>>>(x);
    k_wconv<<<(F_OUT * F_IN + 255) / 256, 256>>>(W);
    k_deg<<<(N_EDGES / 8 + 255) / 256, 256>>>(dst);
    k_scan<<<1, 1024>>>();
    k_fill<<<(N_EDGES / 4 + 255) / 256, 256>>>(src, dst);
    k_gather<<<(N_NODES * 32 + 255) / 256, 256>>>(x);
    dim3 gg((N_NODES + GBM - 1) / GBM, F_OUT / GBN);
    k_gemm_mma<<<gg, 256, GEMM_SMEM_BYTES>>>(b, out);
}

// round 9
// speedup vs baseline: 1.6386x; 1.0829x over previous
#include <cuda_runtime.h>
#include <cuda_bf16.h>
#include <cuda_fp16.h>
#include <cstdint>

#define N_NODES 10000
#define N_EDGES 640000
#define F_IN    128
#define F_OUT   512

// ---------------- device scratch ----------------
__device__ int   g_deg[N_NODES];
__device__ int   g_off[N_NODES];
__device__ int   g_total;          // allocation cursor for CSR segments
__device__ int   g_rank[N_EDGES];
__device__ int   g_csr[N_EDGES];
// x converted to fp16 (row-major, 128 per row)
__device__ __align__(16) __half g_x16[N_NODES * F_IN];
// h as packed bf16 hi/lo rows (128 bf16 = 256B per row)
__device__ __align__(16) unsigned short g_hh[N_NODES * F_IN];
__device__ __align__(16) unsigned short g_hl[N_NODES * F_IN];
// W transposed to [n][k], bf16 hi/lo
__device__ __align__(16) unsigned short g_wt_hi[F_OUT * F_IN];
__device__ __align__(16) unsigned short g_wt_lo[F_OUT * F_IN];

__device__ __forceinline__ void split_bf16(float v, unsigned short& h, unsigned short& l) {
    __nv_bfloat16 bh = __float2bfloat16(v);
    __nv_bfloat16 bl = __float2bfloat16(v - __bfloat162float(bh));
    h = __bfloat16_as_ushort(bh);
    l = __bfloat16_as_ushort(bl);
}

// ---------------- fused conversions: x -> fp16, W -> transposed bf16 hi/lo ---
#define XCONV_ITEMS (N_NODES * F_IN / 4)      // 320000 float4s
#define WCONV_ITEMS (F_OUT * F_IN)            // 65536 elements
__global__ void k_conv(const float* __restrict__ x, const float* __restrict__ W) {
    int i = blockIdx.x * blockDim.x + threadIdx.x;
    if (i == 0) g_total = 0;
    if (i < XCONV_ITEMS) {
        float4 v = ((const float4*)x)[i];
        __half2 a = __floats2half2_rn(v.x, v.y);
        __half2 b = __floats2half2_rn(v.z, v.w);
        ((uint2*)g_x16)[i] = make_uint2(*(uint32_t*)&a, *(uint32_t*)&b);
    } else {
        int idx = i - XCONV_ITEMS;
        if (idx < WCONV_ITEMS) {
            int n = idx >> 7, k = idx & 127;
            float v = W[(size_t)k * F_OUT + n];
            unsigned short h, l;
            split_bf16(v, h, l);
            g_wt_hi[idx] = h;
            g_wt_lo[idx] = l;
        }
    }
}

// ---------------- count in-degree + record per-edge rank (8 edges/thread) ----
__global__ void k_deg(const int* __restrict__ dst) {
    int t = blockIdx.x * blockDim.x + threadIdx.x;
    int e = t * 8;
    if (e < N_EDGES) {
        int4 a = *(const int4*)&dst[e];
        int4 b = *(const int4*)&dst[e + 4];
        int r0 = atomicAdd(&g_deg[a.x], 1);
        int r1 = atomicAdd(&g_deg[a.y], 1);
        int r2 = atomicAdd(&g_deg[a.z], 1);
        int r3 = atomicAdd(&g_deg[a.w], 1);
        int r4 = atomicAdd(&g_deg[b.x], 1);
        int r5 = atomicAdd(&g_deg[b.y], 1);
        int r6 = atomicAdd(&g_deg[b.z], 1);
        int r7 = atomicAdd(&g_deg[b.w], 1);
        *(int4*)&g_rank[e]     = make_int4(r0, r1, r2, r3);
        *(int4*)&g_rank[e + 4] = make_int4(r4, r5, r6, r7);
    }
}

// ---------------- segment allocation: warp-aggregated cursor -----------------
// CSR segments need not be in node order; each warp prefix-sums 32 degs and
// claims a contiguous range with ONE atomicAdd (313 atomics total, all-SM).
__global__ void k_off() {
    int i = blockIdx.x * blockDim.x + threadIdx.x;
    int lane = threadIdx.x & 31;
    int d = (i < N_NODES) ? g_deg[i] : 0;
    int inc = d;
#pragma unroll
    for (int o = 1; o < 32; o <<= 1) {
        int v = __shfl_up_sync(~0u, inc, o);
        if (lane >= o) inc += v;
    }
    int wsum = __shfl_sync(~0u, inc, 31);
    int base = 0;
    if (lane == 31) base = atomicAdd(&g_total, wsum);
    base = __shfl_sync(~0u, base, 31);
    if (i < N_NODES) g_off[i] = base + inc - d;
}

// ---------------- fill CSR (atomic-free), 4 edges/thread ---------------------
__global__ void k_fill(const int* __restrict__ src, const int* __restrict__ dst) {
    int t = blockIdx.x * blockDim.x + threadIdx.x;
    int e = t * 4;
    if (e < N_EDGES) {
        int4 d4 = *(const int4*)&dst[e];
        int4 s4 = *(const int4*)&src[e];
        int4 r4 = *(const int4*)&g_rank[e];
        int o0 = g_off[d4.x], o1 = g_off[d4.y], o2 = g_off[d4.z], o3 = g_off[d4.w];
        g_csr[o0 + r4.x] = s4.x;
        g_csr[o1 + r4.y] = s4.y;
        g_csr[o2 + r4.z] = s4.z;
        g_csr[o3 + r4.w] = s4.w;
    }
}

// ---------------- gather-mean (fp16 reads) -> bf16 hi/lo rows ----------------
__global__ void k_gather(const float* __restrict__ x) {
    int gw = (blockIdx.x * blockDim.x + threadIdx.x) >> 5;
    int lane = threadIdx.x & 31;
    if (gw >= N_NODES) return;

    const uint2* __restrict__ x2 = (const uint2*)g_x16;   // 32 uint2 per row
    int d = g_deg[gw];
    int beg = g_off[gw];
    int end = beg + d;

    float ax = 0.f, ay = 0.f, az = 0.f, aw = 0.f;
    int j = beg;
    for (; j + 7 < end; j += 8) {
        int s0 = g_csr[j + 0], s1 = g_csr[j + 1], s2 = g_csr[j + 2], s3 = g_csr[j + 3];
        int s4 = g_csr[j + 4], s5 = g_csr[j + 5], s6 = g_csr[j + 6], s7 = g_csr[j + 7];
        uint2 c0 = x2[s0 * 32 + lane];
        uint2 c1 = x2[s1 * 32 + lane];
        uint2 c2 = x2[s2 * 32 + lane];
        uint2 c3 = x2[s3 * 32 + lane];
        uint2 c4 = x2[s4 * 32 + lane];
        uint2 c5 = x2[s5 * 32 + lane];
        uint2 c6 = x2[s6 * 32 + lane];
        uint2 c7 = x2[s7 * 32 + lane];
#define ACC(c)                                                     \
        {                                                          \
            float2 f0 = __half22float2(*(__half2*)&(c).x);         \
            float2 f1 = __half22float2(*(__half2*)&(c).y);         \
            ax += f0.x; ay += f0.y; az += f1.x; aw += f1.y;        \
        }
        ACC(c0) ACC(c1) ACC(c2) ACC(c3) ACC(c4) ACC(c5) ACC(c6) ACC(c7)
    }
    for (; j < end; ++j) {
        int s = g_csr[j];
        uint2 c = x2[s * 32 + lane];
        ACC(c)
    }
#undef ACC

    float4 o;
    if (d > 0) {
        float inv = 1.0f / (float)d;
        o.x = ax * inv; o.y = ay * inv; o.z = az * inv; o.w = aw * inv;
    } else {
        // zero-in-degree: keep EXACT fp32 inputs
        o = ((const float4*)x)[gw * 32 + lane];
    }

    unsigned short h0, h1, h2, h3, l0, l1, l2, l3;
    split_bf16(o.x, h0, l0);
    split_bf16(o.y, h1, l1);
    split_bf16(o.z, h2, l2);
    split_bf16(o.w, h3, l3);
    uint2 hv = make_uint2(((uint32_t)h1 << 16) | h0, ((uint32_t)h3 << 16) | h2);
    uint2 lv = make_uint2(((uint32_t)l1 << 16) | l0, ((uint32_t)l3 << 16) | l2);
    int base = gw * F_IN + lane * 4;
    *(uint2*)&g_hh[base] = hv;
    *(uint2*)&g_hl[base] = lv;
}

// ---------------- mma.sync bf16 GEMM (inputs pre-split) ----------------------
#define GBM 128
#define GBN 128
#define APITCH 528
#define A_BYTES (128 * APITCH)
#define GEMM_SMEM_BYTES (2 * A_BYTES + 256)

__device__ __forceinline__ uint32_t smem_u32(const void* p) {
    uint32_t a;
    asm("{ .reg .u64 t; cvta.to.shared.u64 t, %1; cvt.u32.u64 %0, t; }"
        : "=r"(a) : "l"(p));
    return a;
}

#define LDMX4(r0, r1, r2, r3, addr)                                             \
    asm volatile("ldmatrix.sync.aligned.m8n8.x4.shared.b16 {%0,%1,%2,%3}, [%4];" \
                 : "=r"(r0), "=r"(r1), "=r"(r2), "=r"(r3) : "r"(addr))

#define MMA16816(c, a0, a1, a2, a3, b0, b1)                                     \
    asm volatile("mma.sync.aligned.m16n8k16.row.col.f32.bf16.bf16.f32 "         \
                 "{%0,%1,%2,%3}, {%4,%5,%6,%7}, {%8,%9}, {%0,%1,%2,%3};"        \
                 : "+f"((c)[0]), "+f"((c)[1]), "+f"((c)[2]), "+f"((c)[3])       \
                 : "r"(a0), "r"(a1), "r"(a2), "r"(a3), "r"(b0), "r"(b1))

__global__ void __launch_bounds__(256, 1)
k_gemm_mma(const float* __restrict__ bias, float* __restrict__ out) {
    extern __shared__ char smem_raw[];
    uint32_t sb0 = smem_u32(smem_raw);
    uint32_t ab = (sb0 + 255) & ~255u;
    char* tb = smem_raw + (ab - sb0);
    const uint32_t B_OFF = A_BYTES;

    int tid = threadIdx.x;
    int wid = tid >> 5, lane = tid & 31;
    int warp_m = wid & 3;
    int warp_n = wid >> 2;
    int m0 = blockIdx.x * GBM;
    int n0 = blockIdx.y * GBN;

    const uint4* __restrict__ hh4 = (const uint4*)g_hh;
    const uint4* __restrict__ hl4 = (const uint4*)g_hl;
    for (int i = tid; i < 128 * 16; i += 256) {
        int m = i >> 4;
        int c = i & 15;
        uint4 hv, lv;
        if (m0 + m < N_NODES) {
            hv = hh4[(size_t)(m0 + m) * 16 + c];
            lv = hl4[(size_t)(m0 + m) * 16 + c];
        } else {
            hv = make_uint4(0, 0, 0, 0);
            lv = make_uint4(0, 0, 0, 0);
        }
        char* row = tb + m * APITCH + c * 16;
        *(uint4*)(row) = hv;
        *(uint4*)(row + 256) = lv;
    }

    const uint4* __restrict__ wh4 = (const uint4*)g_wt_hi;
    const uint4* __restrict__ wl4 = (const uint4*)g_wt_lo;
    for (int i = tid; i < 128 * 16; i += 256) {
        int n = i >> 4;
        int c = i & 15;
        uint4 hv = wh4[(size_t)(n0 + n) * 16 + c];
        uint4 lv = wl4[(size_t)(n0 + n) * 16 + c];
        char* row = tb + B_OFF + n * APITCH + c * 16;
        *(uint4*)(row) = hv;
        *(uint4*)(row + 256) = lv;
    }
    __syncthreads();

    float acc[2][8][4] = {};

    int a_row = (lane & 15);
    int a_koff = (lane >> 4) << 4;
    int b_nrow = ((lane >> 4) << 3) + (lane & 7);
    int b_koff = ((lane >> 3) & 1) << 4;

#pragma unroll
    for (int pass = 0; pass < 3; pass++) {
        uint32_t abase = (pass < 2) ? 0u : 256u;
        uint32_t bbase = (pass == 1) ? 256u : 0u;
#pragma unroll
        for (int kk = 0; kk < 8; kk++) {
            uint32_t kb = kk * 32;
            uint32_t a0, a1, a2, a3, a4, a5, a6, a7;
            {
                uint32_t addr0 = ab + (uint32_t)((warp_m * 32 + a_row) * APITCH) +
                                 abase + kb + a_koff;
                uint32_t addr1 = addr0 + 16 * APITCH;
                LDMX4(a0, a1, a2, a3, addr0);
                LDMX4(a4, a5, a6, a7, addr1);
            }
#pragma unroll
            for (int nt2 = 0; nt2 < 4; nt2++) {
                uint32_t baddr = ab + B_OFF +
                                 (uint32_t)((warp_n * 64 + nt2 * 16 + b_nrow) * APITCH) +
                                 bbase + kb + b_koff;
                uint32_t b0, b1, b2, b3;
                LDMX4(b0, b1, b2, b3, baddr);
                MMA16816(acc[0][nt2 * 2 + 0], a0, a1, a2, a3, b0, b1);
                MMA16816(acc[1][nt2 * 2 + 0], a4, a5, a6, a7, b0, b1);
                MMA16816(acc[0][nt2 * 2 + 1], a0, a1, a2, a3, b2, b3);
                MMA16816(acc[1][nt2 * 2 + 1], a4, a5, a6, a7, b2, b3);
            }
        }
    }

    int g = lane >> 2;
    int t = lane & 3;
#pragma unroll
    for (int mt = 0; mt < 2; mt++) {
        int row0 = m0 + warp_m * 32 + mt * 16 + g;
        int row1 = row0 + 8;
#pragma unroll
        for (int nt = 0; nt < 8; nt++) {
            int col = n0 + warp_n * 64 + nt * 8 + t * 2;
            float2 bv = *(const float2*)&bias[col];
            if (row0 < N_NODES) {
                float2 o = make_float2(acc[mt][nt][0] + bv.x, acc[mt][nt][1] + bv.y);
                *(float2*)&out[(size_t)row0 * F_OUT + col] = o;
            }
            if (row1 < N_NODES) {
                float2 o = make_float2(acc[mt][nt][2] + bv.x, acc[mt][nt][3] + bv.y);
                *(float2*)&out[(size_t)row1 * F_OUT + col] = o;
            }
        }
    }
}

// ---------------- launch ----------------
extern "C" void kernel_launch(void* const* d_in, const int* in_sizes, int n_in,
                              void* d_out, int out_size) {
    const float* x   = (const float*)d_in[0];
    const int*   src = (const int*)d_in[1];
    const int*   dst = (const int*)d_in[2];
    const float* W   = (const float*)d_in[3];
    const float* b   = (const float*)d_in[4];
    float* out = (float*)d_out;

    cudaFuncSetAttribute(k_gemm_mma, cudaFuncAttributeMaxDynamicSharedMemorySize,
                         GEMM_SMEM_BYTES);

    void* degp = nullptr;
    cudaGetSymbolAddress(&degp, g_deg);
    cudaMemsetAsync(degp, 0, N_NODES * sizeof(int));

    k_conv<<<(XCONV_ITEMS + WCONV_ITEMS + 255) / 256, 256>>>(x, W);
    k_deg<<<(N_EDGES / 8 + 255) / 256, 256>>>(dst);
    k_off<<<(N_NODES + 1023) / 1024, 1024>>>();
    k_fill<<<(N_EDGES / 4 + 255) / 256, 256>>>(src, dst);
    k_gather<<<(N_NODES * 32 + 255) / 256, 256>>>(x);
    dim3 gg((N_NODES + GBM - 1) / GBM, F_OUT / GBN);
    k_gemm_mma<<<gg, 256, GEMM_SMEM_BYTES>>>(b, out);
}